// round 6
// baseline (speedup 1.0000x reference)
#include <cuda_runtime.h>
#include <math.h>
#include <stdint.h>

#define NNODES 50000
#define NEDGES 500000
#define FDIM   128
#define CLS    40

// ---------------- scratch (static device globals; no allocation) ------------
__device__ float g_A   [NNODES * FDIM];   // A' = x @ W_top + b_pre (fp32)
__device__ float g_B   [NNODES * FDIM];   // B  = x @ W_bot        (fp32)
__device__ float g_S   [NNODES * FDIM];   // SUM aggregator  (fp32)
__device__ float g_M   [NNODES * FDIM];   // MAX aggregator  (fp32)
__device__ float g_H   [NNODES * FDIM];   // hidden after layer 1 (fp32)
__device__ float g_H2  [NNODES * FDIM];   // hidden after layer 2 (fp32)
__device__ float g_IC  [NNODES + 128];    // 1/max(cnt,1) per node (padded)
__device__ float g_Wf  [513 * FDIM];      // fused W' (512 rows, tf32) + fused bias (fp32)
__device__ float g_WpreR[2 * 256 * FDIM]; // tf32-rounded w1_pre, w2_pre
__device__ float g_WoR [FDIM * CLS];      // tf32-rounded w_out
__device__ int   g_hist[NNODES];
__device__ int   g_off [NNODES + 1];
__device__ int   g_cur [NNODES];
__device__ int   g_ssrc[NEDGES];          // src ids grouped (counting-sorted) by dst

// ---------------- helpers ---------------------------------------------------
__device__ __forceinline__ float tf32r(float x) {
    unsigned u;
    asm("cvt.rna.tf32.f32 %0, %1;" : "=r"(u) : "f"(x));
    return __uint_as_float(u);
}

__device__ __forceinline__ unsigned tf32u(float x) {
    unsigned u;
    asm("cvt.rna.tf32.f32 %0, %1;" : "=r"(u) : "f"(x));
    return u;
}

__device__ __forceinline__ void cpasync16(void* dst, const void* src, bool pred) {
    unsigned sa = (unsigned)__cvta_generic_to_shared(dst);
    int sz = pred ? 16 : 0;
    asm volatile("cp.async.cg.shared.global [%0], [%1], 16, %2;\n"
                 :: "r"(sa), "l"(src), "r"(sz));
}

__device__ __forceinline__ void mma_tf32(float* c, const unsigned* a,
                                         unsigned b0, unsigned b1) {
    asm volatile(
        "mma.sync.aligned.m16n8k8.row.col.f32.tf32.tf32.f32 "
        "{%0,%1,%2,%3}, {%4,%5,%6,%7}, {%8,%9}, {%0,%1,%2,%3};"
        : "+f"(c[0]), "+f"(c[1]), "+f"(c[2]), "+f"(c[3])
        : "r"(a[0]), "r"(a[1]), "r"(a[2]), "r"(a[3]), "r"(b0), "r"(b1));
}

// ---------------- graph preprocessing ---------------------------------------
__global__ void hist_kernel(const int* __restrict__ dst) {
    int i = blockIdx.x * blockDim.x + threadIdx.x;
    if (i < NEDGES) atomicAdd(&g_hist[dst[i]], 1);
}

__global__ void scan_kernel() {  // 1 block, 1024 threads
    __shared__ int s[1024];
    const int t = threadIdx.x;
    const int chunk = (NNODES + 1023) / 1024;
    int beg = t * chunk;
    int end = beg + chunk; if (end > NNODES) end = NNODES;
    int sum = 0;
    for (int i = beg; i < end; i++) sum += g_hist[i];
    s[t] = sum;
    __syncthreads();
    for (int d = 1; d < 1024; d <<= 1) {
        int v = (t >= d) ? s[t - d] : 0;
        __syncthreads();
        s[t] += v;
        __syncthreads();
    }
    int run = (t > 0) ? s[t - 1] : 0;
    for (int i = beg; i < end; i++) { g_off[i] = run; run += g_hist[i]; }
    if (t == 0) g_off[NNODES] = NEDGES;
}

__global__ void scatter_kernel(const int* __restrict__ src, const int* __restrict__ dst) {
    int i = blockIdx.x * blockDim.x + threadIdx.x;
    if (i >= NEDGES) return;
    int d = dst[i];
    int p = g_off[d] + atomicAdd(&g_cur[d], 1);
    g_ssrc[p] = src[i];
}

// tf32-round all weight matrices in a single launch
#define CVT_N1 (256 * FDIM)
#define CVT_N2 (256 * FDIM)
#define CVT_N3 (FDIM * CLS)
__global__ void cvt_all_kernel(const float* __restrict__ w1,
                               const float* __restrict__ w2,
                               const float* __restrict__ wo) {
    int i = blockIdx.x * blockDim.x + threadIdx.x;
    if (i < CVT_N1) g_WpreR[i] = tf32r(w1[i]);
    else if (i < CVT_N1 + CVT_N2) g_WpreR[i] = tf32r(w2[i - CVT_N1]);
    else if (i < CVT_N1 + CVT_N2 + CVT_N3) g_WoR[i - CVT_N1 - CVT_N2] =
        tf32r(wo[i - CVT_N1 - CVT_N2]);
}

// ---------------- aggregation (warp/node, float4 lanes, unroll 4) ------------
__global__ void aggregate_kernel() {
    int node = (blockIdx.x * blockDim.x + threadIdx.x) >> 5;
    if (node >= NNODES) return;
    int lane = threadIdx.x & 31;
    int beg = g_off[node], end = g_off[node + 1];
    const float4* Bv = (const float4*)g_B;
    float4 s = make_float4(0.f, 0.f, 0.f, 0.f);
    float4 m = make_float4(-3.4e38f, -3.4e38f, -3.4e38f, -3.4e38f);
    int e = beg;
    for (; e + 3 < end; e += 4) {
        int sv0 = __ldg(&g_ssrc[e]);
        int sv1 = __ldg(&g_ssrc[e + 1]);
        int sv2 = __ldg(&g_ssrc[e + 2]);
        int sv3 = __ldg(&g_ssrc[e + 3]);
        float4 v0 = __ldg(&Bv[(size_t)sv0 * 32 + lane]);
        float4 v1 = __ldg(&Bv[(size_t)sv1 * 32 + lane]);
        float4 v2 = __ldg(&Bv[(size_t)sv2 * 32 + lane]);
        float4 v3 = __ldg(&Bv[(size_t)sv3 * 32 + lane]);
        s.x += (v0.x + v1.x) + (v2.x + v3.x);
        s.y += (v0.y + v1.y) + (v2.y + v3.y);
        s.z += (v0.z + v1.z) + (v2.z + v3.z);
        s.w += (v0.w + v1.w) + (v2.w + v3.w);
        m.x = fmaxf(m.x, fmaxf(fmaxf(v0.x, v1.x), fmaxf(v2.x, v3.x)));
        m.y = fmaxf(m.y, fmaxf(fmaxf(v0.y, v1.y), fmaxf(v2.y, v3.y)));
        m.z = fmaxf(m.z, fmaxf(fmaxf(v0.z, v1.z), fmaxf(v2.z, v3.z)));
        m.w = fmaxf(m.w, fmaxf(fmaxf(v0.w, v1.w), fmaxf(v2.w, v3.w)));
    }
    for (; e < end; e++) {
        int sv = __ldg(&g_ssrc[e]);
        float4 v = __ldg(&Bv[(size_t)sv * 32 + lane]);
        s.x += v.x; s.y += v.y; s.z += v.z; s.w += v.w;
        m.x = fmaxf(m.x, v.x); m.y = fmaxf(m.y, v.y);
        m.z = fmaxf(m.z, v.z); m.w = fmaxf(m.w, v.w);
    }
    size_t o = (size_t)node * 32 + lane;
    float c = (float)(end - beg);
    float ic = 1.f / fmaxf(c, 1.f);
    if (lane == 0) g_IC[node] = ic;
    float4 a = ((const float4*)g_A)[o];
    float4 t;
    t.x = fmaf(c, a.x, s.x); t.y = fmaf(c, a.y, s.y);
    t.z = fmaf(c, a.z, s.z); t.w = fmaf(c, a.w, s.w);
    ((float4*)g_S)[o] = t;
    bool nz = (c > 0.f);
    float4 mx;
    mx.x = nz ? (a.x + m.x) : 0.f; mx.y = nz ? (a.y + m.y) : 0.f;
    mx.z = nz ? (a.z + m.z) : 0.f; mx.w = nz ? (a.w + m.w) : 0.f;
    ((float4*)g_M)[o] = mx;
}

// ---------------- W' = [w_post; b_post] @ w_lin (+ b_lin on bias row) -------
__global__ void fuse_kernel(const float* __restrict__ wpost, const float* __restrict__ bpost,
                            const float* __restrict__ wlin,  const float* __restrict__ blin) {
    __shared__ float srow[FDIM];
    int r = blockIdx.x;    // 0..512
    int c = threadIdx.x;   // 0..127
    const float* row = (r < 512) ? (wpost + (size_t)r * FDIM) : bpost;
    srow[c] = row[c];
    __syncthreads();
    float acc = (r == 512) ? blin[c] : 0.f;
    #pragma unroll 8
    for (int k = 0; k < FDIM; k++) acc = fmaf(srow[k], wlin[k * FDIM + c], acc);
    g_Wf[r * FDIM + c] = (r < 512) ? tf32r(acc) : acc;  // bias row stays fp32
}

// ---------------- TF32 tensor-core GEMM (templated N tile) -------------------
// NT = number of 8-col n-subtiles per warp. NT=8 -> block N=128; NT=4 -> N=64.
// mode 0: blockIdx.x selects weight matrix half + output (dual pre-GEMM).
// mode 1: blockIdx.x selects column half of W/out (wave-quantization split).
// SCALE template in mma_block applies per-row ic to the mean segment only.
#define ASTRIDE 36

struct GemmSrcs { const float* s[4]; };

template<int NT, bool SCALE>
__device__ __forceinline__ void mma_block(const float* __restrict__ As,
                                          const float* __restrict__ Bs,
                                          float (*acc)[NT][4],
                                          int wm, int wn, int fr, int fc,
                                          const float* fs) {
    constexpr int BST = NT * 16 + 8;
    #pragma unroll
    for (int kk = 0; kk < 32; kk += 8) {
        float v0 = As[(wm + fr)      * ASTRIDE + kk + fc];
        float v1 = As[(wm + fr + 8)  * ASTRIDE + kk + fc];
        float v2 = As[(wm + fr)      * ASTRIDE + kk + fc + 4];
        float v3 = As[(wm + fr + 8)  * ASTRIDE + kk + fc + 4];
        float v4 = As[(wm + fr + 16) * ASTRIDE + kk + fc];
        float v5 = As[(wm + fr + 24) * ASTRIDE + kk + fc];
        float v6 = As[(wm + fr + 16) * ASTRIDE + kk + fc + 4];
        float v7 = As[(wm + fr + 24) * ASTRIDE + kk + fc + 4];
        if (SCALE) {
            v0 *= fs[0]; v1 *= fs[1]; v2 *= fs[0]; v3 *= fs[1];
            v4 *= fs[2]; v5 *= fs[3]; v6 *= fs[2]; v7 *= fs[3];
        }
        unsigned af0[4] = {tf32u(v0), tf32u(v1), tf32u(v2), tf32u(v3)};
        unsigned af1[4] = {tf32u(v4), tf32u(v5), tf32u(v6), tf32u(v7)};
        #pragma unroll
        for (int nt = 0; nt < NT; nt++) {
            int n0 = wn + nt * 8;
            unsigned b0 = __float_as_uint(Bs[(kk + fc)     * BST + n0 + fr]);
            unsigned b1 = __float_as_uint(Bs[(kk + 4 + fc) * BST + n0 + fr]);
            mma_tf32(acc[0][nt], af0, b0, b1);
            mma_tf32(acc[1][nt], af1, b0, b1);
        }
    }
}

template<int NT>
__global__ __launch_bounds__(256, 2)
void mma_gemm(GemmSrcs srcs, const float* __restrict__ W,
              const float* __restrict__ bias0,
              float* outA, float* outB,
              const float* __restrict__ icvec, int meanSeg,
              int M, int nIter, int relu, int mode) {
    constexpr int BST  = NT * 16 + 8;
    constexpr int F4R  = NT * 4;               // float4 per B row
    constexpr int STG  = 128 * ASTRIDE + 32 * BST;
    constexpr int NCOL = NT * 16;              // block N width
    extern __shared__ float smem[];
    const int tid = threadIdx.x;
    const int bm = blockIdx.y * 128;

    const float* Wb = W;
    float* out = outA;
    const float* bias = bias0;
    int ncol0 = 0;
    if (mode == 0 && blockIdx.x == 1) {
        Wb = W + 128 * 128;
        out = outB;
        bias = nullptr;
    }
    if (mode == 1) ncol0 = blockIdx.x * NCOL;

    const int lane = tid & 31, wid = tid >> 5;
    const int wm = (wid >> 1) * 32, wn = (wid & 1) * NT * 8;
    const int fr = lane >> 2, fc = lane & 3;

    float fs[4] = {1.f, 1.f, 1.f, 1.f};
    if (icvec) {
        int r = bm + wm + fr;
        fs[0] = icvec[r];      fs[1] = icvec[r + 8];
        fs[2] = icvec[r + 16]; fs[3] = icvec[r + 24];
    }

    float acc[2][NT][4];
    #pragma unroll
    for (int mt = 0; mt < 2; mt++)
        #pragma unroll
        for (int nt = 0; nt < NT; nt++)
            #pragma unroll
            for (int j = 0; j < 4; j++) acc[mt][nt][j] = 0.f;

    auto loadStage = [&](int it, int stage) {
        int k0 = it * 32;
        const float* sp = srcs.s[(k0 >> 7) & 3];
        int kloc = k0 & 127;
        float* As = smem + stage * STG;
        float* Bs = As + 128 * ASTRIDE;
        #pragma unroll
        for (int i = 0; i < 4; i++) {
            int id = tid + 256 * i;
            int arow = id >> 3, c4 = id & 7;
            bool p = (bm + arow) < M;
            cpasync16(As + arow * ASTRIDE + c4 * 4,
                      sp + (size_t)(bm + arow) * 128 + kloc + c4 * 4, p);
        }
        #pragma unroll
        for (int i = 0; i < F4R / 8; i++) {
            int id = tid + 256 * i;
            int krow = id / F4R, c4 = id % F4R;
            cpasync16(Bs + krow * BST + c4 * 4,
                      Wb + (size_t)(k0 + krow) * 128 + ncol0 + c4 * 4, true);
        }
        asm volatile("cp.async.commit_group;" ::: "memory");
    };

    loadStage(0, 0);
    for (int it = 0; it < nIter; ++it) {
        int cur = it & 1;
        if (it + 1 < nIter) {
            loadStage(it + 1, cur ^ 1);
            asm volatile("cp.async.wait_group 1;" ::: "memory");
        } else {
            asm volatile("cp.async.wait_group 0;" ::: "memory");
        }
        __syncthreads();

        const float* As = smem + cur * STG;
        const float* Bs = As + 128 * ASTRIDE;
        bool ms = (((it * 32) >> 7) == meanSeg);
        if (ms) mma_block<NT, true >(As, Bs, acc, wm, wn, fr, fc, fs);
        else    mma_block<NT, false>(As, Bs, acc, wm, wn, fr, fc, fs);
        __syncthreads();
    }

    #pragma unroll
    for (int mt = 0; mt < 2; mt++) {
        #pragma unroll
        for (int nt = 0; nt < NT; nt++) {
            int r0 = bm + wm + mt * 16 + fr;
            int cc = ncol0 + wn + nt * 8 + 2 * fc;
            float b0 = 0.f, b1 = 0.f;
            if (bias) { b0 = bias[cc]; b1 = bias[cc + 1]; }
            float v0 = acc[mt][nt][0] + b0, v1 = acc[mt][nt][1] + b1;
            float v2 = acc[mt][nt][2] + b0, v3 = acc[mt][nt][3] + b1;
            if (relu) {
                v0 = fmaxf(v0, 0.f); v1 = fmaxf(v1, 0.f);
                v2 = fmaxf(v2, 0.f); v3 = fmaxf(v3, 0.f);
            }
            if (r0 < M) {
                float2 o = make_float2(v0, v1);
                *(float2*)(out + (size_t)r0 * 128 + cc) = o;
            }
            if (r0 + 8 < M) {
                float2 o = make_float2(v2, v3);
                *(float2*)(out + (size_t)(r0 + 8) * 128 + cc) = o;
            }
        }
    }
}

#define SMEM8_BYTES ((128 * ASTRIDE + 32 * (8 * 16 + 8)) * 2 * 4)
#define SMEM4_BYTES ((128 * ASTRIDE + 32 * (4 * 16 + 8)) * 2 * 4)

// ---------------- TF32 MMA output projection: out = H2 @ Wo + b -------------
#define OAST 132
#define OBST 44
#define OSMEM_F (128 * OAST + 128 * OBST)
#define OSMEM_BYTES (OSMEM_F * 4)

__global__ __launch_bounds__(256, 2)
void out_gemm(const float* __restrict__ H2, const float* __restrict__ Wo,
              const float* __restrict__ bias, float* __restrict__ out, int M) {
    extern __shared__ float smem[];
    float* As = smem;
    float* Bs = smem + 128 * OAST;
    const int tid = threadIdx.x;
    const int bm = blockIdx.x * 128;
    const int lane = tid & 31, wid = tid >> 5;
    const int fr = lane >> 2, fc = lane & 3;

    #pragma unroll
    for (int i = 0; i < 16; i++) {
        int id = tid + 256 * i;
        int arow = id >> 5, c4 = id & 31;
        bool p = (bm + arow) < M;
        cpasync16(As + arow * OAST + c4 * 4,
                  H2 + (size_t)(bm + arow) * 128 + c4 * 4, p);
    }
    #pragma unroll
    for (int i = 0; i < 5; i++) {
        int id = tid + 256 * i;
        int wrow = id / 10, c4 = id % 10;
        cpasync16(Bs + wrow * OBST + c4 * 4,
                  Wo + (size_t)wrow * CLS + c4 * 4, true);
    }
    asm volatile("cp.async.commit_group;" ::: "memory");
    asm volatile("cp.async.wait_group 0;" ::: "memory");
    __syncthreads();

    const int m0 = wid * 16;
    float acc[5][4];
    #pragma unroll
    for (int nt = 0; nt < 5; nt++)
        #pragma unroll
        for (int j = 0; j < 4; j++) acc[nt][j] = 0.f;

    #pragma unroll
    for (int kk = 0; kk < 128; kk += 8) {
        unsigned af[4];
        af[0] = tf32u(As[(m0 + fr)     * OAST + kk + fc]);
        af[1] = tf32u(As[(m0 + fr + 8) * OAST + kk + fc]);
        af[2] = tf32u(As[(m0 + fr)     * OAST + kk + fc + 4]);
        af[3] = tf32u(As[(m0 + fr + 8) * OAST + kk + fc + 4]);
        #pragma unroll
        for (int nt = 0; nt < 5; nt++) {
            int n0 = nt * 8;
            unsigned b0 = __float_as_uint(Bs[(kk + fc)     * OBST + n0 + fr]);
            unsigned b1 = __float_as_uint(Bs[(kk + 4 + fc) * OBST + n0 + fr]);
            mma_tf32(acc[nt], af, b0, b1);
        }
    }

    #pragma unroll
    for (int nt = 0; nt < 5; nt++) {
        int r0 = bm + m0 + fr;
        int cc = nt * 8 + 2 * fc;
        float b0 = bias[cc], b1 = bias[cc + 1];
        if (r0 < M) {
            float2 o = make_float2(acc[nt][0] + b0, acc[nt][1] + b1);
            *(float2*)(out + (size_t)r0 * CLS + cc) = o;
        }
        if (r0 + 8 < M) {
            float2 o = make_float2(acc[nt][2] + b0, acc[nt][3] + b1);
            *(float2*)(out + (size_t)(r0 + 8) * CLS + cc) = o;
        }
    }
}

// ---------------- host side -------------------------------------------------
extern "C" void kernel_launch(void* const* d_in, const int* in_sizes, int n_in,
                              void* d_out, int out_size) {
    const float* x      = (const float*)d_in[0];
    const int*   ei     = (const int*)  d_in[1];
    const float* w1_pre = (const float*)d_in[2];
    const float* b1_pre = (const float*)d_in[3];
    const float* w1_post= (const float*)d_in[4];
    const float* b1_post= (const float*)d_in[5];
    const float* w1_lin = (const float*)d_in[6];
    const float* b1_lin = (const float*)d_in[7];
    const float* w2_pre = (const float*)d_in[8];
    const float* b2_pre = (const float*)d_in[9];
    const float* w2_post= (const float*)d_in[10];
    const float* b2_post= (const float*)d_in[11];
    const float* w2_lin = (const float*)d_in[12];
    const float* b2_lin = (const float*)d_in[13];
    const float* w_out  = (const float*)d_in[14];
    const float* b_out  = (const float*)d_in[15];
    float* out = (float*)d_out;

    static int init_done = 0;
    static cudaStream_t side = nullptr;
    static cudaEvent_t evFork = nullptr, evJoin = nullptr;
    if (!init_done) {
        cudaFuncSetAttribute(mma_gemm<8>, cudaFuncAttributeMaxDynamicSharedMemorySize,
                             SMEM8_BYTES);
        cudaFuncSetAttribute(mma_gemm<4>, cudaFuncAttributeMaxDynamicSharedMemorySize,
                             SMEM4_BYTES);
        cudaFuncSetAttribute(out_gemm, cudaFuncAttributeMaxDynamicSharedMemorySize,
                             OSMEM_BYTES);
        cudaStreamCreateWithFlags(&side, cudaStreamNonBlocking);
        cudaEventCreateWithFlags(&evFork, cudaEventDisableTiming);
        cudaEventCreateWithFlags(&evJoin, cudaEventDisableTiming);
        init_done = 1;
    }

    void *pA, *pB, *pH, *pH2, *pS, *pM, *pIC, *pWf, *pWpreR, *pWoR, *pHist, *pCur;
    cudaGetSymbolAddress(&pA, g_A);
    cudaGetSymbolAddress(&pB, g_B);
    cudaGetSymbolAddress(&pH, g_H);
    cudaGetSymbolAddress(&pH2, g_H2);
    cudaGetSymbolAddress(&pS, g_S);
    cudaGetSymbolAddress(&pM, g_M);
    cudaGetSymbolAddress(&pIC, g_IC);
    cudaGetSymbolAddress(&pWf, g_Wf);
    cudaGetSymbolAddress(&pWpreR, g_WpreR);
    cudaGetSymbolAddress(&pWoR, g_WoR);
    cudaGetSymbolAddress(&pHist, g_hist);
    cudaGetSymbolAddress(&pCur, g_cur);

    const int* srcp = ei;           // edge_index[0]
    const int* dstp = ei + NEDGES;  // edge_index[1]

    // ---- fork: graph preprocessing on side stream (overlaps layer-1 GEMM) --
    cudaEventRecord(evFork, 0);
    cudaStreamWaitEvent(side, evFork, 0);
    cudaMemsetAsync(pHist, 0, NNODES * sizeof(int), side);
    cudaMemsetAsync(pCur,  0, NNODES * sizeof(int), side);
    hist_kernel<<<(NEDGES + 255) / 256, 256, 0, side>>>(dstp);
    scan_kernel<<<1, 1024, 0, side>>>();
    scatter_kernel<<<(NEDGES + 255) / 256, 256, 0, side>>>(srcp, dstp);
    cudaEventRecord(evJoin, side);

    // ---- main stream: weights + layer-1 pre-GEMM (edge-independent) --------
    const int cvt_total = CVT_N1 + CVT_N2 + CVT_N3;
    cvt_all_kernel<<<(cvt_total + 255) / 256, 256>>>(w1_pre, w2_pre, w_out);

    const int MB = (NNODES + 127) / 128;
    GemmSrcs pre1; pre1.s[0] = x; pre1.s[1] = x; pre1.s[2] = x; pre1.s[3] = x;
    mma_gemm<8><<<dim3(2, MB), 256, SMEM8_BYTES>>>(
        pre1, (const float*)pWpreR, b1_pre, (float*)pA, (float*)pB,
        nullptr, -1, NNODES, 128 / 32, 0, 0);
    fuse_kernel<<<513, 128>>>(w1_post, b1_post, w1_lin, b1_lin);

    // ---- join: aggregation needs sorted edges ------------------------------
    cudaStreamWaitEvent(0, evJoin, 0);
    aggregate_kernel<<<(NNODES + 7) / 8, 256>>>();

    GemmSrcs cat1; cat1.s[0] = x; cat1.s[1] = (const float*)pS;
    cat1.s[2] = (const float*)pM; cat1.s[3] = (const float*)pS;
    mma_gemm<4><<<dim3(2, MB), 256, SMEM4_BYTES>>>(
        cat1, (const float*)pWf, (const float*)pWf + 512 * FDIM,
        (float*)pH, (float*)pH, (const float*)pIC, 1, NNODES, 512 / 32, 1, 1);

    // ---- layer 2 -----------------------------------------------------------
    GemmSrcs pre2; pre2.s[0] = (const float*)pH; pre2.s[1] = pre2.s[0];
    pre2.s[2] = pre2.s[0]; pre2.s[3] = pre2.s[0];
    mma_gemm<8><<<dim3(2, MB), 256, SMEM8_BYTES>>>(
        pre2, (const float*)pWpreR + 256 * FDIM, b2_pre, (float*)pA, (float*)pB,
        nullptr, -1, NNODES, 128 / 32, 0, 0);
    fuse_kernel<<<513, 128>>>(w2_post, b2_post, w2_lin, b2_lin);
    aggregate_kernel<<<(NNODES + 7) / 8, 256>>>();

    GemmSrcs cat2; cat2.s[0] = (const float*)pH; cat2.s[1] = (const float*)pS;
    cat2.s[2] = (const float*)pM; cat2.s[3] = (const float*)pS;
    mma_gemm<4><<<dim3(2, MB), 256, SMEM4_BYTES>>>(
        cat2, (const float*)pWf, (const float*)pWf + 512 * FDIM,
        (float*)pH2, (float*)pH2, (const float*)pIC, 1, NNODES, 512 / 32, 1, 1);

    // ---- output projection (TF32 MMA) --------------------------------------
    out_gemm<<<(NNODES + 127) / 128, 256, OSMEM_BYTES>>>(
        (const float*)pH2, (const float*)pWoR, b_out, out, NNODES);
}

// round 7
// speedup vs baseline: 1.0701x; 1.0701x over previous
#include <cuda_runtime.h>
#include <math.h>
#include <stdint.h>

#define NNODES 50000
#define NEDGES 500000
#define FDIM   128
#define CLS    40

// ---------------- scratch (static device globals; no allocation) ------------
__device__ float g_A   [NNODES * FDIM];   // A' = x @ W_top + b_pre (fp32)
__device__ float g_B   [NNODES * FDIM];   // B  = x @ W_bot        (fp32)
__device__ float g_S   [NNODES * FDIM];   // SUM aggregator  (fp32)
__device__ float g_M   [NNODES * FDIM];   // MAX aggregator  (fp32)
__device__ float g_H   [NNODES * FDIM];   // hidden after layer 1 (fp32)
__device__ float g_H2  [NNODES * FDIM];   // hidden after layer 2 (fp32)
__device__ float g_IC  [NNODES + 128];    // 1/max(cnt,1) per node (padded)
__device__ float g_Wf  [513 * FDIM];      // fused W' (512 rows, tf32) + fused bias (fp32)
__device__ float g_WpreR[2 * 256 * FDIM]; // tf32-rounded w1_pre, w2_pre
__device__ float g_WoR [FDIM * CLS];      // tf32-rounded w_out
__device__ int   g_hist[NNODES];
__device__ int   g_off [NNODES + 1];
__device__ int   g_cur [NNODES];
__device__ int   g_ssrc[NEDGES];          // src ids grouped (counting-sorted) by dst

// ---------------- helpers ---------------------------------------------------
__device__ __forceinline__ float tf32r(float x) {
    unsigned u;
    asm("cvt.rna.tf32.f32 %0, %1;" : "=r"(u) : "f"(x));
    return __uint_as_float(u);
}

__device__ __forceinline__ unsigned tf32u(float x) {
    unsigned u;
    asm("cvt.rna.tf32.f32 %0, %1;" : "=r"(u) : "f"(x));
    return u;
}

__device__ __forceinline__ void cpasync16(void* dst, const void* src, bool pred) {
    unsigned sa = (unsigned)__cvta_generic_to_shared(dst);
    int sz = pred ? 16 : 0;
    asm volatile("cp.async.cg.shared.global [%0], [%1], 16, %2;\n"
                 :: "r"(sa), "l"(src), "r"(sz));
}

__device__ __forceinline__ void mma_tf32(float* c, const unsigned* a,
                                         unsigned b0, unsigned b1) {
    asm volatile(
        "mma.sync.aligned.m16n8k8.row.col.f32.tf32.tf32.f32 "
        "{%0,%1,%2,%3}, {%4,%5,%6,%7}, {%8,%9}, {%0,%1,%2,%3};"
        : "+f"(c[0]), "+f"(c[1]), "+f"(c[2]), "+f"(c[3])
        : "r"(a[0]), "r"(a[1]), "r"(a[2]), "r"(a[3]), "r"(b0), "r"(b1));
}

// ---------------- graph preprocessing ---------------------------------------
__global__ void hist_kernel(const int* __restrict__ dst) {
    int i = blockIdx.x * blockDim.x + threadIdx.x;
    if (i < NEDGES) atomicAdd(&g_hist[dst[i]], 1);
}

__global__ void scan_kernel() {  // 1 block, 1024 threads
    __shared__ int s[1024];
    const int t = threadIdx.x;
    const int chunk = (NNODES + 1023) / 1024;
    int beg = t * chunk;
    int end = beg + chunk; if (end > NNODES) end = NNODES;
    int sum = 0;
    for (int i = beg; i < end; i++) sum += g_hist[i];
    s[t] = sum;
    __syncthreads();
    for (int d = 1; d < 1024; d <<= 1) {
        int v = (t >= d) ? s[t - d] : 0;
        __syncthreads();
        s[t] += v;
        __syncthreads();
    }
    int run = (t > 0) ? s[t - 1] : 0;
    for (int i = beg; i < end; i++) { g_off[i] = run; run += g_hist[i]; }
    if (t == 0) g_off[NNODES] = NEDGES;
}

__global__ void scatter_kernel(const int* __restrict__ src, const int* __restrict__ dst) {
    int i = blockIdx.x * blockDim.x + threadIdx.x;
    if (i >= NEDGES) return;
    int d = dst[i];
    int p = g_off[d] + atomicAdd(&g_cur[d], 1);
    g_ssrc[p] = src[i];
}

// tf32-round all weight matrices in a single launch
#define CVT_N1 (256 * FDIM)
#define CVT_N2 (256 * FDIM)
#define CVT_N3 (FDIM * CLS)
__global__ void cvt_all_kernel(const float* __restrict__ w1,
                               const float* __restrict__ w2,
                               const float* __restrict__ wo) {
    int i = blockIdx.x * blockDim.x + threadIdx.x;
    if (i < CVT_N1) g_WpreR[i] = tf32r(w1[i]);
    else if (i < CVT_N1 + CVT_N2) g_WpreR[i] = tf32r(w2[i - CVT_N1]);
    else if (i < CVT_N1 + CVT_N2 + CVT_N3) g_WoR[i - CVT_N1 - CVT_N2] =
        tf32r(wo[i - CVT_N1 - CVT_N2]);
}

// ---------------- aggregation (warp/node, float4 lanes, unroll 4) ------------
__global__ void aggregate_kernel() {
    int node = (blockIdx.x * blockDim.x + threadIdx.x) >> 5;
    if (node >= NNODES) return;
    int lane = threadIdx.x & 31;
    int beg = g_off[node], end = g_off[node + 1];
    const float4* Bv = (const float4*)g_B;
    float4 s = make_float4(0.f, 0.f, 0.f, 0.f);
    float4 m = make_float4(-3.4e38f, -3.4e38f, -3.4e38f, -3.4e38f);
    int e = beg;
    for (; e + 3 < end; e += 4) {
        int sv0 = __ldg(&g_ssrc[e]);
        int sv1 = __ldg(&g_ssrc[e + 1]);
        int sv2 = __ldg(&g_ssrc[e + 2]);
        int sv3 = __ldg(&g_ssrc[e + 3]);
        float4 v0 = __ldg(&Bv[(size_t)sv0 * 32 + lane]);
        float4 v1 = __ldg(&Bv[(size_t)sv1 * 32 + lane]);
        float4 v2 = __ldg(&Bv[(size_t)sv2 * 32 + lane]);
        float4 v3 = __ldg(&Bv[(size_t)sv3 * 32 + lane]);
        s.x += (v0.x + v1.x) + (v2.x + v3.x);
        s.y += (v0.y + v1.y) + (v2.y + v3.y);
        s.z += (v0.z + v1.z) + (v2.z + v3.z);
        s.w += (v0.w + v1.w) + (v2.w + v3.w);
        m.x = fmaxf(m.x, fmaxf(fmaxf(v0.x, v1.x), fmaxf(v2.x, v3.x)));
        m.y = fmaxf(m.y, fmaxf(fmaxf(v0.y, v1.y), fmaxf(v2.y, v3.y)));
        m.z = fmaxf(m.z, fmaxf(fmaxf(v0.z, v1.z), fmaxf(v2.z, v3.z)));
        m.w = fmaxf(m.w, fmaxf(fmaxf(v0.w, v1.w), fmaxf(v2.w, v3.w)));
    }
    for (; e < end; e++) {
        int sv = __ldg(&g_ssrc[e]);
        float4 v = __ldg(&Bv[(size_t)sv * 32 + lane]);
        s.x += v.x; s.y += v.y; s.z += v.z; s.w += v.w;
        m.x = fmaxf(m.x, v.x); m.y = fmaxf(m.y, v.y);
        m.z = fmaxf(m.z, v.z); m.w = fmaxf(m.w, v.w);
    }
    size_t o = (size_t)node * 32 + lane;
    float c = (float)(end - beg);
    float ic = 1.f / fmaxf(c, 1.f);
    if (lane == 0) g_IC[node] = ic;
    float4 a = ((const float4*)g_A)[o];
    float4 t;
    t.x = fmaf(c, a.x, s.x); t.y = fmaf(c, a.y, s.y);
    t.z = fmaf(c, a.z, s.z); t.w = fmaf(c, a.w, s.w);
    ((float4*)g_S)[o] = t;
    bool nz = (c > 0.f);
    float4 mx;
    mx.x = nz ? (a.x + m.x) : 0.f; mx.y = nz ? (a.y + m.y) : 0.f;
    mx.z = nz ? (a.z + m.z) : 0.f; mx.w = nz ? (a.w + m.w) : 0.f;
    ((float4*)g_M)[o] = mx;
}

// ---------------- W' = [w_post; b_post] @ w_lin (+ b_lin on bias row) -------
__global__ void fuse_kernel(const float* __restrict__ wpost, const float* __restrict__ bpost,
                            const float* __restrict__ wlin,  const float* __restrict__ blin) {
    __shared__ float srow[FDIM];
    int r = blockIdx.x;    // 0..512
    int c = threadIdx.x;   // 0..127
    const float* row = (r < 512) ? (wpost + (size_t)r * FDIM) : bpost;
    srow[c] = row[c];
    __syncthreads();
    float acc = (r == 512) ? blin[c] : 0.f;
    #pragma unroll 8
    for (int k = 0; k < FDIM; k++) acc = fmaf(srow[k], wlin[k * FDIM + c], acc);
    g_Wf[r * FDIM + c] = (r < 512) ? tf32r(acc) : acc;  // bias row stays fp32
}

// ---------------- TF32 tensor-core GEMM (block 128x128, K-slab 32) -----------
// R4 structure (NT=8, no N split). SCALE variant of the inner block applies
// per-row ic to the mean segment only (cat-GEMM iterations 4-7), compiled in
// only on that path — pre-GEMMs never see the multiply.
#define ASTRIDE 36
#define BSTRIDE 136
#define STAGEF  (128 * ASTRIDE + 32 * BSTRIDE)
#define SMEM_BYTES (2 * STAGEF * 4)

struct GemmSrcs { const float* s[4]; };

template<bool SCALE>
__device__ __forceinline__ void mma_block(const float* __restrict__ As,
                                          const float* __restrict__ Bs,
                                          float (*acc)[8][4],
                                          int wm, int wn, int fr, int fc,
                                          const float* fs) {
    #pragma unroll
    for (int kk = 0; kk < 32; kk += 8) {
        float v0 = As[(wm + fr)      * ASTRIDE + kk + fc];
        float v1 = As[(wm + fr + 8)  * ASTRIDE + kk + fc];
        float v2 = As[(wm + fr)      * ASTRIDE + kk + fc + 4];
        float v3 = As[(wm + fr + 8)  * ASTRIDE + kk + fc + 4];
        float v4 = As[(wm + fr + 16) * ASTRIDE + kk + fc];
        float v5 = As[(wm + fr + 24) * ASTRIDE + kk + fc];
        float v6 = As[(wm + fr + 16) * ASTRIDE + kk + fc + 4];
        float v7 = As[(wm + fr + 24) * ASTRIDE + kk + fc + 4];
        if (SCALE) {
            v0 *= fs[0]; v1 *= fs[1]; v2 *= fs[0]; v3 *= fs[1];
            v4 *= fs[2]; v5 *= fs[3]; v6 *= fs[2]; v7 *= fs[3];
        }
        unsigned af0[4] = {tf32u(v0), tf32u(v1), tf32u(v2), tf32u(v3)};
        unsigned af1[4] = {tf32u(v4), tf32u(v5), tf32u(v6), tf32u(v7)};
        #pragma unroll
        for (int nt = 0; nt < 8; nt++) {
            int n0 = wn + nt * 8;
            unsigned b0 = __float_as_uint(Bs[(kk + fc)     * BSTRIDE + n0 + fr]);
            unsigned b1 = __float_as_uint(Bs[(kk + 4 + fc) * BSTRIDE + n0 + fr]);
            mma_tf32(acc[0][nt], af0, b0, b1);
            mma_tf32(acc[1][nt], af1, b0, b1);
        }
    }
}

__global__ __launch_bounds__(256, 2)
void mma_gemm(GemmSrcs srcs, const float* __restrict__ W,
              const float* __restrict__ bias0,
              float* outA, float* outB,
              const float* __restrict__ icvec, int meanSeg,
              int M, int nIter, int relu) {
    extern __shared__ float smem[];
    const int tid = threadIdx.x;
    const int bm = blockIdx.y * 128;

    const float* Wb = W;
    float* out = outA;
    const float* bias = bias0;
    if (gridDim.x == 2 && blockIdx.x == 1) {
        Wb = W + 128 * 128;
        out = outB;
        bias = nullptr;
    }

    const int lane = tid & 31, wid = tid >> 5;
    const int wm = (wid >> 1) * 32, wn = (wid & 1) * 64;
    const int fr = lane >> 2, fc = lane & 3;

    float fs[4] = {1.f, 1.f, 1.f, 1.f};
    if (icvec) {
        int r = bm + wm + fr;
        fs[0] = icvec[r];      fs[1] = icvec[r + 8];
        fs[2] = icvec[r + 16]; fs[3] = icvec[r + 24];
    }

    float acc[2][8][4];
    #pragma unroll
    for (int mt = 0; mt < 2; mt++)
        #pragma unroll
        for (int nt = 0; nt < 8; nt++)
            #pragma unroll
            for (int j = 0; j < 4; j++) acc[mt][nt][j] = 0.f;

    auto loadStage = [&](int it, int stage) {
        int k0 = it * 32;
        const float* sp = srcs.s[(k0 >> 7) & 3];
        int kloc = k0 & 127;
        float* As = smem + stage * STAGEF;
        float* Bs = As + 128 * ASTRIDE;
        #pragma unroll
        for (int i = 0; i < 4; i++) {
            int id = tid + 256 * i;
            int arow = id >> 3, c4 = id & 7;
            bool p = (bm + arow) < M;
            cpasync16(As + arow * ASTRIDE + c4 * 4,
                      sp + (size_t)(bm + arow) * 128 + kloc + c4 * 4, p);
        }
        #pragma unroll
        for (int i = 0; i < 4; i++) {
            int id = tid + 256 * i;
            int krow = id >> 5, c4 = id & 31;
            cpasync16(Bs + krow * BSTRIDE + c4 * 4,
                      Wb + (size_t)(k0 + krow) * 128 + c4 * 4, true);
        }
        asm volatile("cp.async.commit_group;" ::: "memory");
    };

    loadStage(0, 0);
    for (int it = 0; it < nIter; ++it) {
        int cur = it & 1;
        if (it + 1 < nIter) {
            loadStage(it + 1, cur ^ 1);
            asm volatile("cp.async.wait_group 1;" ::: "memory");
        } else {
            asm volatile("cp.async.wait_group 0;" ::: "memory");
        }
        __syncthreads();

        const float* As = smem + cur * STAGEF;
        const float* Bs = As + 128 * ASTRIDE;
        bool ms = (((it * 32) >> 7) == meanSeg);
        if (ms) mma_block<true >(As, Bs, acc, wm, wn, fr, fc, fs);
        else    mma_block<false>(As, Bs, acc, wm, wn, fr, fc, fs);
        __syncthreads();
    }

    #pragma unroll
    for (int mt = 0; mt < 2; mt++) {
        #pragma unroll
        for (int nt = 0; nt < 8; nt++) {
            int r0 = bm + wm + mt * 16 + fr;
            int cc = wn + nt * 8 + 2 * fc;
            float b0 = 0.f, b1 = 0.f;
            if (bias) { b0 = bias[cc]; b1 = bias[cc + 1]; }
            float v0 = acc[mt][nt][0] + b0, v1 = acc[mt][nt][1] + b1;
            float v2 = acc[mt][nt][2] + b0, v3 = acc[mt][nt][3] + b1;
            if (relu) {
                v0 = fmaxf(v0, 0.f); v1 = fmaxf(v1, 0.f);
                v2 = fmaxf(v2, 0.f); v3 = fmaxf(v3, 0.f);
            }
            if (r0 < M) {
                float2 o = make_float2(v0, v1);
                *(float2*)(out + (size_t)r0 * 128 + cc) = o;
            }
            if (r0 + 8 < M) {
                float2 o = make_float2(v2, v3);
                *(float2*)(out + (size_t)(r0 + 8) * 128 + cc) = o;
            }
        }
    }
}

// ---------------- TF32 MMA output projection: out = H2 @ Wo + b -------------
#define OAST 132
#define OBST 44
#define OSMEM_F (128 * OAST + 128 * OBST)
#define OSMEM_BYTES (OSMEM_F * 4)

__global__ __launch_bounds__(256, 2)
void out_gemm(const float* __restrict__ H2, const float* __restrict__ Wo,
              const float* __restrict__ bias, float* __restrict__ out, int M) {
    extern __shared__ float smem[];
    float* As = smem;
    float* Bs = smem + 128 * OAST;
    const int tid = threadIdx.x;
    const int bm = blockIdx.x * 128;
    const int lane = tid & 31, wid = tid >> 5;
    const int fr = lane >> 2, fc = lane & 3;

    #pragma unroll
    for (int i = 0; i < 16; i++) {
        int id = tid + 256 * i;
        int arow = id >> 5, c4 = id & 31;
        bool p = (bm + arow) < M;
        cpasync16(As + arow * OAST + c4 * 4,
                  H2 + (size_t)(bm + arow) * 128 + c4 * 4, p);
    }
    #pragma unroll
    for (int i = 0; i < 5; i++) {
        int id = tid + 256 * i;
        int wrow = id / 10, c4 = id % 10;
        cpasync16(Bs + wrow * OBST + c4 * 4,
                  Wo + (size_t)wrow * CLS + c4 * 4, true);
    }
    asm volatile("cp.async.commit_group;" ::: "memory");
    asm volatile("cp.async.wait_group 0;" ::: "memory");
    __syncthreads();

    const int m0 = wid * 16;
    float acc[5][4];
    #pragma unroll
    for (int nt = 0; nt < 5; nt++)
        #pragma unroll
        for (int j = 0; j < 4; j++) acc[nt][j] = 0.f;

    #pragma unroll
    for (int kk = 0; kk < 128; kk += 8) {
        unsigned af[4];
        af[0] = tf32u(As[(m0 + fr)     * OAST + kk + fc]);
        af[1] = tf32u(As[(m0 + fr + 8) * OAST + kk + fc]);
        af[2] = tf32u(As[(m0 + fr)     * OAST + kk + fc + 4]);
        af[3] = tf32u(As[(m0 + fr + 8) * OAST + kk + fc + 4]);
        #pragma unroll
        for (int nt = 0; nt < 5; nt++) {
            int n0 = nt * 8;
            unsigned b0 = __float_as_uint(Bs[(kk + fc)     * OBST + n0 + fr]);
            unsigned b1 = __float_as_uint(Bs[(kk + 4 + fc) * OBST + n0 + fr]);
            mma_tf32(acc[nt], af, b0, b1);
        }
    }

    #pragma unroll
    for (int nt = 0; nt < 5; nt++) {
        int r0 = bm + m0 + fr;
        int cc = nt * 8 + 2 * fc;
        float b0 = bias[cc], b1 = bias[cc + 1];
        if (r0 < M) {
            float2 o = make_float2(acc[nt][0] + b0, acc[nt][1] + b1);
            *(float2*)(out + (size_t)r0 * CLS + cc) = o;
        }
        if (r0 + 8 < M) {
            float2 o = make_float2(acc[nt][2] + b0, acc[nt][3] + b1);
            *(float2*)(out + (size_t)(r0 + 8) * CLS + cc) = o;
        }
    }
}

// ---------------- host side -------------------------------------------------
extern "C" void kernel_launch(void* const* d_in, const int* in_sizes, int n_in,
                              void* d_out, int out_size) {
    const float* x      = (const float*)d_in[0];
    const int*   ei     = (const int*)  d_in[1];
    const float* w1_pre = (const float*)d_in[2];
    const float* b1_pre = (const float*)d_in[3];
    const float* w1_post= (const float*)d_in[4];
    const float* b1_post= (const float*)d_in[5];
    const float* w1_lin = (const float*)d_in[6];
    const float* b1_lin = (const float*)d_in[7];
    const float* w2_pre = (const float*)d_in[8];
    const float* b2_pre = (const float*)d_in[9];
    const float* w2_post= (const float*)d_in[10];
    const float* b2_post= (const float*)d_in[11];
    const float* w2_lin = (const float*)d_in[12];
    const float* b2_lin = (const float*)d_in[13];
    const float* w_out  = (const float*)d_in[14];
    const float* b_out  = (const float*)d_in[15];
    float* out = (float*)d_out;

    static int init_done = 0;
    static cudaStream_t side = nullptr;
    static cudaEvent_t evFork = nullptr, evJoin = nullptr;
    if (!init_done) {
        cudaFuncSetAttribute(mma_gemm, cudaFuncAttributeMaxDynamicSharedMemorySize,
                             SMEM_BYTES);
        cudaFuncSetAttribute(out_gemm, cudaFuncAttributeMaxDynamicSharedMemorySize,
                             OSMEM_BYTES);
        cudaStreamCreateWithFlags(&side, cudaStreamNonBlocking);
        cudaEventCreateWithFlags(&evFork, cudaEventDisableTiming);
        cudaEventCreateWithFlags(&evJoin, cudaEventDisableTiming);
        init_done = 1;
    }

    void *pA, *pB, *pH, *pH2, *pS, *pM, *pIC, *pWf, *pWpreR, *pWoR, *pHist, *pCur;
    cudaGetSymbolAddress(&pA, g_A);
    cudaGetSymbolAddress(&pB, g_B);
    cudaGetSymbolAddress(&pH, g_H);
    cudaGetSymbolAddress(&pH2, g_H2);
    cudaGetSymbolAddress(&pS, g_S);
    cudaGetSymbolAddress(&pM, g_M);
    cudaGetSymbolAddress(&pIC, g_IC);
    cudaGetSymbolAddress(&pWf, g_Wf);
    cudaGetSymbolAddress(&pWpreR, g_WpreR);
    cudaGetSymbolAddress(&pWoR, g_WoR);
    cudaGetSymbolAddress(&pHist, g_hist);
    cudaGetSymbolAddress(&pCur, g_cur);

    const int* srcp = ei;           // edge_index[0]
    const int* dstp = ei + NEDGES;  // edge_index[1]

    // ---- fork: graph preprocessing on side stream (overlaps layer-1 GEMM) --
    cudaEventRecord(evFork, 0);
    cudaStreamWaitEvent(side, evFork, 0);
    cudaMemsetAsync(pHist, 0, NNODES * sizeof(int), side);
    cudaMemsetAsync(pCur,  0, NNODES * sizeof(int), side);
    hist_kernel<<<(NEDGES + 255) / 256, 256, 0, side>>>(dstp);
    scan_kernel<<<1, 1024, 0, side>>>();
    scatter_kernel<<<(NEDGES + 255) / 256, 256, 0, side>>>(srcp, dstp);
    cudaEventRecord(evJoin, side);

    // ---- main stream: weights + layer-1 pre-GEMM (edge-independent) --------
    const int cvt_total = CVT_N1 + CVT_N2 + CVT_N3;
    cvt_all_kernel<<<(cvt_total + 255) / 256, 256>>>(w1_pre, w2_pre, w_out);

    const int MB = (NNODES + 127) / 128;
    GemmSrcs pre1; pre1.s[0] = x; pre1.s[1] = x; pre1.s[2] = x; pre1.s[3] = x;
    mma_gemm<<<dim3(2, MB), 256, SMEM_BYTES>>>(
        pre1, (const float*)pWpreR, b1_pre, (float*)pA, (float*)pB,
        nullptr, -1, NNODES, 128 / 32, 0);
    fuse_kernel<<<513, 128>>>(w1_post, b1_post, w1_lin, b1_lin);

    // ---- join: aggregation needs sorted edges ------------------------------
    cudaStreamWaitEvent(0, evJoin, 0);
    aggregate_kernel<<<(NNODES + 7) / 8, 256>>>();

    GemmSrcs cat1; cat1.s[0] = x; cat1.s[1] = (const float*)pS;
    cat1.s[2] = (const float*)pM; cat1.s[3] = (const float*)pS;
    mma_gemm<<<dim3(1, MB), 256, SMEM_BYTES>>>(
        cat1, (const float*)pWf, (const float*)pWf + 512 * FDIM,
        (float*)pH, (float*)pH, (const float*)pIC, 1, NNODES, 512 / 32, 1);

    // ---- layer 2 -----------------------------------------------------------
    GemmSrcs pre2; pre2.s[0] = (const float*)pH; pre2.s[1] = pre2.s[0];
    pre2.s[2] = pre2.s[0]; pre2.s[3] = pre2.s[0];
    mma_gemm<<<dim3(2, MB), 256, SMEM_BYTES>>>(
        pre2, (const float*)pWpreR + 256 * FDIM, b2_pre, (float*)pA, (float*)pB,
        nullptr, -1, NNODES, 128 / 32, 0);
    fuse_kernel<<<513, 128>>>(w2_post, b2_post, w2_lin, b2_lin);
    aggregate_kernel<<<(NNODES + 7) / 8, 256>>>();

    GemmSrcs cat2; cat2.s[0] = (const float*)pH; cat2.s[1] = (const float*)pS;
    cat2.s[2] = (const float*)pM; cat2.s[3] = (const float*)pS;
    mma_gemm<<<dim3(1, MB), 256, SMEM_BYTES>>>(
        cat2, (const float*)pWf, (const float*)pWf + 512 * FDIM,
        (float*)pH2, (float*)pH2, (const float*)pIC, 1, NNODES, 512 / 32, 1);

    // ---- output projection (TF32 MMA) --------------------------------------
    out_gemm<<<(NNODES + 127) / 128, 256, OSMEM_BYTES>>>(
        (const float*)pH2, (const float*)pWoR, b_out, out, NNODES);
}